// round 6
// baseline (speedup 1.0000x reference)
#include <cuda_runtime.h>
#include <cuda_bf16.h>
#include <math_constants.h>
#include <cstdint>

// ============================================================================
// Exact k-NN: coarse bf16 mma.sync GEMM + exact fp32 rescore (base-PTX only).
//   1) bsqcvt:  |b|^2 + bf16 copy of base (single pass); small cvt for query
//   2) coarse:  warp-tiled m16n8k16 bf16 MMA, fused per-query top-16/chunk
//               on key = |b|^2 - 2*dot  (|q|^2 rank-invariant)
//   3) merge:   37 chunk lists -> global top-32 per query (coalesced layout)
//   4) rescore: exact fp32 d2 of 32 candidates, sort, emit top-k
// R6 = R5 resubmit (container infra failure, kernel never ran). Fixes vs R4:
//   * last tile: wait_group 0 (was: empty commit + wait_group 1 -> read of
//     in-flight tile)
//   * trailing __syncthreads() after scan: kills cross-thread race between
//     scan(sBsq[s]) and next iteration's prefetch into the same slot
// ============================================================================

#define D128  128
#define NC    37        // base chunks
#define NT    32        // base rows per tile
#define KCC   16        // candidates per (query, chunk)
#define KG    32        // global coarse candidates per query
#define MAXN  262144
#define MAXQ  1024
#define PADW  136       // bf16 per padded row (272 B)
#define ROWB  272
#define BUFB  (NT * ROWB)   // 8704 B per B buffer

__device__ __align__(256) __nv_bfloat16 g_bhi[MAXN * D128];
__device__ __align__(256) __nv_bfloat16 g_qhi[MAXQ * D128];
__device__ float g_bsq[MAXN];
__device__ float g_qsq_dummy[MAXQ];
__device__ float g_ckey[NC * KCC * MAXQ];
__device__ int   g_cidx[NC * KCC * MAXQ];
__device__ int   g_sel [MAXQ * KG];

// ------------------------------- helpers -----------------------------------
__device__ __forceinline__ uint32_t smem_u32(const void* p) {
    uint32_t a;
    asm("{ .reg .u64 t; cvta.to.shared.u64 t, %1; cvt.u32.u64 %0, t; }"
        : "=r"(a) : "l"(p));
    return a;
}
#define CP_ASYNC16(dst, src) \
    asm volatile("cp.async.cg.shared.global [%0], [%1], 16;" :: "r"(dst), "l"(src) : "memory")
#define CP_ASYNC4(dst, src) \
    asm volatile("cp.async.ca.shared.global [%0], [%1], 4;" :: "r"(dst), "l"(src) : "memory")
#define CP_COMMIT() asm volatile("cp.async.commit_group;" ::: "memory")
#define CP_WAIT0()  asm volatile("cp.async.wait_group 0;" ::: "memory")
#define CP_WAIT1()  asm volatile("cp.async.wait_group 1;" ::: "memory")

__device__ __forceinline__ void ldsm_x4(uint32_t* r, uint32_t addr) {
    asm volatile("ldmatrix.sync.aligned.m8n8.x4.shared.b16 {%0,%1,%2,%3}, [%4];"
                 : "=r"(r[0]), "=r"(r[1]), "=r"(r[2]), "=r"(r[3]) : "r"(addr));
}
__device__ __forceinline__ void mma16816(float* c, const uint32_t* a,
                                         uint32_t b0, uint32_t b1) {
    asm volatile(
        "mma.sync.aligned.m16n8k16.row.col.f32.bf16.bf16.f32 "
        "{%0,%1,%2,%3}, {%4,%5,%6,%7}, {%8,%9}, {%0,%1,%2,%3};"
        : "+f"(c[0]), "+f"(c[1]), "+f"(c[2]), "+f"(c[3])
        : "r"(a[0]), "r"(a[1]), "r"(a[2]), "r"(a[3]), "r"(b0), "r"(b1));
}

template<int K> __device__ __forceinline__
void topk_insert(float (&td)[K], int (&ti)[K], float& kmax, float v, int idx) {
    bool done = false;
    #pragma unroll
    for (int s = 0; s < K; ++s)
        if (!done && td[s] == kmax) { td[s] = v; ti[s] = idx; done = true; }
    float m = td[0];
    #pragma unroll
    for (int s = 1; s < K; ++s) m = fmaxf(m, td[s]);
    kmax = m;
}

// ---------------------------------------------------------------------------
// Fused |row|^2 + fp32->bf16 convert. One warp per row.
// ---------------------------------------------------------------------------
__global__ void bsqcvt_kernel(const float* __restrict__ src,
                              __nv_bfloat16* __restrict__ dst,
                              float* __restrict__ sq, int N) {
    int row = blockIdx.x * 8 + (threadIdx.x >> 5);
    if (row >= N) return;
    int lane = threadIdx.x & 31;
    float4 v = reinterpret_cast<const float4*>(src)[(size_t)row * 32 + lane];
    __nv_bfloat162 lo = __floats2bfloat162_rn(v.x, v.y);
    __nv_bfloat162 hi = __floats2bfloat162_rn(v.z, v.w);
    __nv_bfloat162* o = reinterpret_cast<__nv_bfloat162*>(dst) + (size_t)row * 64 + lane * 2;
    o[0] = lo; o[1] = hi;
    float s = v.x * v.x + v.y * v.y + v.z * v.z + v.w * v.w;
    #pragma unroll
    for (int off = 16; off > 0; off >>= 1) s += __shfl_xor_sync(0xFFFFFFFFu, s, off);
    if (lane == 0) sq[row] = s;
}

// ---------------------------------------------------------------------------
// Coarse: grid (NC, Q/128), block 256. Warp w owns query rows [w*16, w*16+16)
// and all 32 base cols of each tile. A fragments register-cached.
// ---------------------------------------------------------------------------
__global__ void __launch_bounds__(256)
knn_coarse(const __nv_bfloat16* __restrict__ bhi,
           const __nv_bfloat16* __restrict__ qhi,
           int N, int Q) {
    __shared__ __align__(16) __nv_bfloat16 sB[2][NT][PADW];   // 17408 B
    __shared__ __align__(16) float sC[128][34];               // 17408 B
    __shared__ float sBsq[2][NT];

    const int tid  = threadIdx.x;
    const int wid  = tid >> 5;
    const int lane = tid & 31;
    const int chunk = blockIdx.x;
    const int qt    = blockIdx.y;

    const uint32_t aSB = smem_u32(&sB[0][0][0]);

    const int chunk_len = (N + NC - 1) / NC;
    const int cs = chunk * chunk_len;
    const int ce = min(cs + chunk_len, N);
    const int ntiles = (ce - cs + NT - 1) / NT;

    // ---------------- stage A (query tile) + cache fragments ----------------
    uint32_t af[8][4];
    #pragma unroll
    for (int p = 0; p < 2; ++p) {
        #pragma unroll
        for (int j = 0; j < 4; ++j) {
            int c = tid + j * 256;            // 0..1023
            int row = c >> 4, ch = c & 15;
            int qg = min(qt * 128 + p * 64 + row, Q - 1);
            const char* src = reinterpret_cast<const char*>(qhi) + (size_t)qg * 256 + ch * 16;
            CP_ASYNC16(aSB + row * ROWB + ch * 16, src);
        }
        CP_COMMIT(); CP_WAIT0();
        __syncthreads();
        if ((wid >> 2) == p) {
            int lrow = wid * 16 - p * 64 + (lane & 15);
            uint32_t base = aSB + lrow * ROWB + ((lane >> 4) << 4);
            #pragma unroll
            for (int ks = 0; ks < 8; ++ks)
                ldsm_x4(af[ks], base + ks * 32);
        }
        __syncthreads();
    }

    // ---------------- top-16 state (1 query per thread, tid<128) ------------
    float td[KCC]; int ti[KCC];
    #pragma unroll
    for (int j = 0; j < KCC; ++j) { td[j] = CUDART_INF_F; ti[j] = -1; }
    float kmax = CUDART_INF_F;

    // ---------------- prefetch tile 0 ---------------------------------------
    {
        const int n0 = cs;
        #pragma unroll
        for (int j = 0; j < 2; ++j) {
            int c = tid + j * 256;            // 0..511
            int row = c >> 4, ch = c & 15;
            int gr = min(n0 + row, N - 1);
            const char* src = reinterpret_cast<const char*>(bhi) + (size_t)gr * 256 + ch * 16;
            CP_ASYNC16(aSB + row * ROWB + ch * 16, src);
        }
        if (tid < NT) {
            int gr = min(n0 + tid, N - 1);
            CP_ASYNC4(smem_u32(&sBsq[0][tid]), &g_bsq[gr]);
        }
        CP_COMMIT();
    }

    // ---------------- main loop ---------------------------------------------
    for (int t = 0; t < ntiles; ++t) {
        const int s = t & 1;
        if (t + 1 < ntiles) {
            // prefetch t+1, then wait for tile t (1 newer group outstanding)
            const int n0 = cs + (t + 1) * NT;
            const int s1 = (t + 1) & 1;
            #pragma unroll
            for (int j = 0; j < 2; ++j) {
                int c = tid + j * 256;
                int row = c >> 4, ch = c & 15;
                int gr = min(n0 + row, N - 1);
                const char* src = reinterpret_cast<const char*>(bhi) + (size_t)gr * 256 + ch * 16;
                CP_ASYNC16(aSB + s1 * BUFB + row * ROWB + ch * 16, src);
            }
            if (tid < NT) {
                int gr = min(n0 + tid, N - 1);
                CP_ASYNC4(smem_u32(&sBsq[s1][tid]), &g_bsq[gr]);
            }
            CP_COMMIT();
            CP_WAIT1();
        } else {
            CP_WAIT0();        // last tile must fully land (no empty-group trick)
        }
        __syncthreads();

        // ---- MMA: 16 queries x 32 base rows, K=128 ----
        float acc[4][4];
        #pragma unroll
        for (int na = 0; na < 4; ++na)
            #pragma unroll
            for (int r = 0; r < 4; ++r) acc[na][r] = 0.f;

        {
            int nrow = ((lane >> 4) << 3) + (lane & 7);
            int kc8  = ((lane >> 3) & 1) << 3;
            uint32_t bbase = aSB + s * BUFB + nrow * ROWB + kc8 * 2;
            #pragma unroll
            for (int ks = 0; ks < 8; ++ks) {
                uint32_t b0[4], b1[4];
                ldsm_x4(b0, bbase + ks * 32);               // n 0-15
                ldsm_x4(b1, bbase + 16 * ROWB + ks * 32);   // n 16-31
                mma16816(acc[0], af[ks], b0[0], b0[1]);
                mma16816(acc[1], af[ks], b0[2], b0[3]);
                mma16816(acc[2], af[ks], b1[0], b1[1]);
                mma16816(acc[3], af[ks], b1[2], b1[3]);
            }
        }

        // ---- store dots to sC: rows = queries, cols = base rows ----
        {
            int r0 = wid * 16 + (lane >> 2);
            int c0 = 2 * (lane & 3);
            #pragma unroll
            for (int na = 0; na < 4; ++na) {
                *reinterpret_cast<float2*>(&sC[r0][na * 8 + c0])     = make_float2(acc[na][0], acc[na][1]);
                *reinterpret_cast<float2*>(&sC[r0 + 8][na * 8 + c0]) = make_float2(acc[na][2], acc[na][3]);
            }
        }
        __syncthreads();

        // ---- scan: thread tid<128 owns query row tid ----
        if (tid < 128) {
            const int n0 = cs + t * NT;
            const int vn = min(NT, ce - n0);
            #pragma unroll 8
            for (int j = 0; j < vn; ++j) {
                float key = fmaf(-2.0f, sC[tid][j], sBsq[s][j]);
                if (key < kmax) topk_insert(td, ti, kmax, key, n0 + j);
            }
        }
        __syncthreads();   // scan done in ALL threads before next
                           // iteration's prefetch overwrites sBsq slot
    }

    // ---- write candidates (transposed for coalesced merge reads) ----
    if (tid < 128) {
        int q = qt * 128 + tid;
        if (q < Q) {
            #pragma unroll
            for (int j = 0; j < KCC; ++j) {
                g_ckey[(chunk * KCC + j) * MAXQ + q] = td[j];
                g_cidx[(chunk * KCC + j) * MAXQ + q] = ti[j];
            }
        }
    }
}

// ---------------------------------------------------------------------------
// Merge NC*16 chunk candidates -> global top-32 per query
// ---------------------------------------------------------------------------
__global__ void merge_kernel(int Q) {
    int q = blockIdx.x * blockDim.x + threadIdx.x;
    if (q >= Q) return;
    float td[KG]; int ti[KG];
    #pragma unroll
    for (int j = 0; j < KG; ++j) { td[j] = CUDART_INF_F; ti[j] = -1; }
    float kmax = CUDART_INF_F;
    for (int j = 0; j < NC * KCC; ++j) {
        float v = g_ckey[j * MAXQ + q];
        if (v < kmax) topk_insert(td, ti, kmax, v, g_cidx[j * MAXQ + q]);
    }
    #pragma unroll
    for (int j = 0; j < KG; ++j) g_sel[q * KG + j] = ti[j];
}

// ---------------------------------------------------------------------------
// Exact fp32 rescore of 32 candidates/query + final sort + output.
// 1 warp per query, lane = candidate.
// ---------------------------------------------------------------------------
__global__ void rescore_kernel(const float* __restrict__ base,
                               const float* __restrict__ query,
                               float* __restrict__ out, int N, int Q, int K) {
    __shared__ float sD[4][KG];
    __shared__ int   sI[4][KG];
    int w = threadIdx.x >> 5;
    int lane = threadIdx.x & 31;
    int q = blockIdx.x * 4 + w;
    if (q >= Q) return;

    int cand = g_sel[q * KG + lane];
    float d2;
    if (cand >= 0) {
        const float4* qrow = reinterpret_cast<const float4*>(query) + (size_t)q * 32;
        const float4* brow = reinterpret_cast<const float4*>(base) + (size_t)cand * 32;
        float dot = 0.f, qsq = 0.f;
        #pragma unroll
        for (int j = 0; j < 32; ++j) {
            float4 a = qrow[j], b = brow[j];
            dot += a.x * b.x + a.y * b.y + a.z * b.z + a.w * b.w;
            qsq += a.x * a.x + a.y * a.y + a.z * a.z + a.w * a.w;
        }
        d2 = qsq - 2.0f * dot + g_bsq[cand];
    } else {
        d2 = CUDART_INF_F; cand = 0x7fffffff;
    }
    sD[w][lane] = d2; sI[w][lane] = cand;
    __syncwarp();

    if (lane == 0) {
        float a[KG]; int b[KG];
        #pragma unroll
        for (int j = 0; j < KG; ++j) { a[j] = sD[w][j]; b[j] = sI[w][j]; }
        for (int r = 0; r < K; ++r) {
            int best = r;
            for (int j = r + 1; j < KG; ++j)
                if (a[j] < a[best] || (a[j] == a[best] && b[j] < b[best])) best = j;
            float tv = a[r]; a[r] = a[best]; a[best] = tv;
            int   ts = b[r]; b[r] = b[best]; b[best] = ts;
            out[(size_t)q * K + r]                 = (float)b[r];
            out[(size_t)Q * K + (size_t)q * K + r] = sqrtf(fmaxf(a[r], 0.0f));
        }
    }
}

// ---------------------------------------------------------------------------
extern "C" void kernel_launch(void* const* d_in, const int* in_sizes, int n_in,
                              void* d_out, int out_size) {
    const float* base  = (const float*)d_in[0];
    const float* query = (const float*)d_in[1];

    int N = in_sizes[0] / D128;
    int Q = in_sizes[1] / D128;
    int K = (Q > 0) ? out_size / (2 * Q) : 10;
    if (K <= 0 || K > KG) K = 10;

    __nv_bfloat16* bhi; cudaGetSymbolAddress((void**)&bhi, g_bhi);
    __nv_bfloat16* qhi; cudaGetSymbolAddress((void**)&qhi, g_qhi);
    float* bsq;  cudaGetSymbolAddress((void**)&bsq, g_bsq);
    float* qsqd; cudaGetSymbolAddress((void**)&qsqd, g_qsq_dummy);

    bsqcvt_kernel<<<(N + 7) / 8, 256>>>(base, bhi, bsq, N);
    bsqcvt_kernel<<<(Q + 7) / 8, 256>>>(query, qhi, qsqd, Q);

    dim3 grid(NC, (Q + 127) / 128);
    knn_coarse<<<grid, 256>>>(bhi, qhi, N, Q);

    merge_kernel<<<(Q + 255) / 256, 256>>>(Q);
    rescore_kernel<<<(Q + 3) / 4, 128>>>(base, query, (float*)d_out, N, Q, K);
}

// round 7
// speedup vs baseline: 1.9715x; 1.9715x over previous
#include <cuda_runtime.h>
#include <cuda_bf16.h>
#include <math_constants.h>
#include <cstdint>

// ============================================================================
// Exact k-NN: coarse bf16 mma.sync GEMM + exact fp32 rescore.
// R7: removed cp.async pipeline (LDG->reg->STS double buffer), NT=64,
//     ONE barrier per tile, top-k filter directly on MMA fragments
//     (no sC smem round-trip, no per-tile scan), end-of-kernel merge.
// ============================================================================

#define D128  128
#define NC    37        // base chunks
#define NT    64        // base rows per tile
#define KCC   16        // candidates per (query, chunk)
#define KPL   8         // per-thread per-row candidate depth
#define KG    32        // global coarse candidates per query
#define MAXN  262144
#define MAXQ  1024
#define PADW  136       // bf16 per padded row
#define ROWB  272       // bytes per padded row
#define BUFB  (NT * ROWB)

__device__ __align__(256) __nv_bfloat16 g_bhi[MAXN * D128];
__device__ __align__(256) __nv_bfloat16 g_qhi[MAXQ * D128];
__device__ float g_bsq[MAXN];
__device__ float g_qsq_dummy[MAXQ];
__device__ float g_ckey[NC * KCC * MAXQ];
__device__ int   g_cidx[NC * KCC * MAXQ];
__device__ int   g_sel [MAXQ * KG];

// ------------------------------- helpers -----------------------------------
__device__ __forceinline__ uint32_t smem_u32(const void* p) {
    uint32_t a;
    asm("{ .reg .u64 t; cvta.to.shared.u64 t, %1; cvt.u32.u64 %0, t; }"
        : "=r"(a) : "l"(p));
    return a;
}
__device__ __forceinline__ void ldsm_x4(uint32_t* r, uint32_t addr) {
    asm volatile("ldmatrix.sync.aligned.m8n8.x4.shared.b16 {%0,%1,%2,%3}, [%4];"
                 : "=r"(r[0]), "=r"(r[1]), "=r"(r[2]), "=r"(r[3]) : "r"(addr));
}
__device__ __forceinline__ void mma16816(float* c, const uint32_t* a,
                                         uint32_t b0, uint32_t b1) {
    asm volatile(
        "mma.sync.aligned.m16n8k16.row.col.f32.bf16.bf16.f32 "
        "{%0,%1,%2,%3}, {%4,%5,%6,%7}, {%8,%9}, {%0,%1,%2,%3};"
        : "+f"(c[0]), "+f"(c[1]), "+f"(c[2]), "+f"(c[3])
        : "r"(a[0]), "r"(a[1]), "r"(a[2]), "r"(a[3]), "r"(b0), "r"(b1));
}

template<int K> __device__ __forceinline__
void topk_insert(float (&td)[K], int (&ti)[K], float& kmax, float v, int idx) {
    bool done = false;
    #pragma unroll
    for (int s = 0; s < K; ++s)
        if (!done && td[s] == kmax) { td[s] = v; ti[s] = idx; done = true; }
    float m = td[0];
    #pragma unroll
    for (int s = 1; s < K; ++s) m = fmaxf(m, td[s]);
    kmax = m;
}

// ---------------------------------------------------------------------------
// Fused |row|^2 + fp32->bf16 convert. One warp per row.
// ---------------------------------------------------------------------------
__global__ void bsqcvt_kernel(const float* __restrict__ src,
                              __nv_bfloat16* __restrict__ dst,
                              float* __restrict__ sq, int N) {
    int row = blockIdx.x * 8 + (threadIdx.x >> 5);
    if (row >= N) return;
    int lane = threadIdx.x & 31;
    float4 v = reinterpret_cast<const float4*>(src)[(size_t)row * 32 + lane];
    __nv_bfloat162 lo = __floats2bfloat162_rn(v.x, v.y);
    __nv_bfloat162 hi = __floats2bfloat162_rn(v.z, v.w);
    __nv_bfloat162* o = reinterpret_cast<__nv_bfloat162*>(dst) + (size_t)row * 64 + lane * 2;
    o[0] = lo; o[1] = hi;
    float s = v.x * v.x + v.y * v.y + v.z * v.z + v.w * v.w;
    #pragma unroll
    for (int off = 16; off > 0; off >>= 1) s += __shfl_xor_sync(0xFFFFFFFFu, s, off);
    if (lane == 0) sq[row] = s;
}

// ---------------------------------------------------------------------------
// Coarse: grid (NC, Q/128), block 256 (8 warps). Warp w owns query rows
// [w*16, w*16+16). NT=64 base rows/tile, LDG->reg->STS double buffer,
// one barrier per tile. Filter runs on MMA fragments in registers.
// ---------------------------------------------------------------------------
__global__ void __launch_bounds__(256)
knn_coarse(const __nv_bfloat16* __restrict__ bhi,
           const __nv_bfloat16* __restrict__ qhi,
           int N, int Q) {
    __shared__ __align__(16) __nv_bfloat16 sB[2][NT][PADW];   // 34816 B
    __shared__ float sBsq[2][NT];

    const int tid  = threadIdx.x;
    const int wid  = tid >> 5;
    const int lane = tid & 31;
    const int chunk = blockIdx.x;
    const int qt    = blockIdx.y;

    const uint32_t aSB = smem_u32(&sB[0][0][0]);
    char* const pSB = reinterpret_cast<char*>(&sB[0][0][0]);

    const int chunk_len = (N + NC - 1) / NC;
    const int cs = chunk * chunk_len;
    const int ce = min(cs + chunk_len, N);
    const int ntiles = (ce - cs + NT - 1) / NT;

    const float4* bhi4 = reinterpret_cast<const float4*>(bhi);
    const float4* qhi4 = reinterpret_cast<const float4*>(qhi);

    // ---------------- stage A (query tile) + cache fragments ----------------
    uint32_t af[8][4];
    #pragma unroll
    for (int p = 0; p < 2; ++p) {
        #pragma unroll
        for (int j = 0; j < 4; ++j) {
            int c = tid + j * 256;            // 0..1023
            int row = c >> 4, ch = c & 15;
            int qg = min(qt * 128 + p * 64 + row, Q - 1);
            float4 v = qhi4[(size_t)qg * 16 + ch];
            *reinterpret_cast<float4*>(pSB + row * ROWB + ch * 16) = v;
        }
        __syncthreads();
        if ((wid >> 2) == p) {
            int lrow = (wid & 3) * 16 + (lane & 15);
            uint32_t base = aSB + lrow * ROWB + ((lane >> 4) << 4);
            #pragma unroll
            for (int ks = 0; ks < 8; ++ks)
                ldsm_x4(af[ks], base + ks * 32);
        }
        __syncthreads();
    }

    // ---------------- per-thread top-8 per query row -------------------------
    float td0[KPL], td1[KPL]; int ti0[KPL], ti1[KPL];
    #pragma unroll
    for (int j = 0; j < KPL; ++j) {
        td0[j] = CUDART_INF_F; ti0[j] = -1;
        td1[j] = CUDART_INF_F; ti1[j] = -1;
    }
    float kmax0 = CUDART_INF_F, kmax1 = CUDART_INF_F;

    // ---------------- prologue: tile 0 -> sB[0] ------------------------------
    {
        #pragma unroll
        for (int j = 0; j < 4; ++j) {
            int c = tid + j * 256;
            int row = c >> 4, ch = c & 15;
            int gr = min(cs + row, N - 1);
            float4 v = bhi4[(size_t)gr * 16 + ch];
            *reinterpret_cast<float4*>(pSB + row * ROWB + ch * 16) = v;
        }
        if (tid < NT) {
            int gr = cs + tid;
            sBsq[0][tid] = (gr < ce) ? g_bsq[gr] : CUDART_INF_F;
        }
        __syncthreads();
    }

    // ---------------- main loop: 1 barrier per tile --------------------------
    for (int t = 0; t < ntiles; ++t) {
        const int s = t & 1;
        const int n0 = cs + t * NT;
        const bool pf = (t + 1 < ntiles);

        // prefetch tile t+1 into registers (lands during MMA phase)
        float4 r0, r1, r2, r3; float rb = CUDART_INF_F;
        if (pf) {
            const int n0n = cs + (t + 1) * NT;
            {
                int c = tid;           int row = c >> 4, ch = c & 15;
                r0 = bhi4[(size_t)min(n0n + row, N - 1) * 16 + ch];
            }
            { int c = tid + 256;       int row = c >> 4, ch = c & 15;
                r1 = bhi4[(size_t)min(n0n + row, N - 1) * 16 + ch]; }
            { int c = tid + 512;       int row = c >> 4, ch = c & 15;
                r2 = bhi4[(size_t)min(n0n + row, N - 1) * 16 + ch]; }
            { int c = tid + 768;       int row = c >> 4, ch = c & 15;
                r3 = bhi4[(size_t)min(n0n + row, N - 1) * 16 + ch]; }
            if (tid < NT) {
                int gr = n0n + tid;
                rb = (gr < ce) ? g_bsq[gr] : CUDART_INF_F;
            }
        }

        // MMA + in-register filter, two n-halves of 32
        const int nrow = ((lane >> 4) << 3) + (lane & 7);
        const int kc8  = ((lane >> 3) & 1) << 3;
        #pragma unroll
        for (int h = 0; h < 2; ++h) {
            float acc[4][4];
            #pragma unroll
            for (int g = 0; g < 4; ++g)
                #pragma unroll
                for (int r = 0; r < 4; ++r) acc[g][r] = 0.f;

            uint32_t bbase = aSB + s * BUFB + (h * 32 + nrow) * ROWB + kc8 * 2;
            #pragma unroll
            for (int ks = 0; ks < 8; ++ks) {
                uint32_t b0[4], b1[4];
                ldsm_x4(b0, bbase + ks * 32);               // n h*32 + 0..15
                ldsm_x4(b1, bbase + 16 * ROWB + ks * 32);   // n h*32 + 16..31
                mma16816(acc[0], af[ks], b0[0], b0[1]);
                mma16816(acc[1], af[ks], b0[2], b0[3]);
                mma16816(acc[2], af[ks], b1[0], b1[1]);
                mma16816(acc[3], af[ks], b1[2], b1[3]);
            }

            // filter: thread covers rows (m_lo, m_lo+8) x 8 n-cols this half
            #pragma unroll
            for (int g = 0; g < 4; ++g) {
                int ncol = h * 32 + g * 8 + 2 * (lane & 3);
                float2 b2 = *reinterpret_cast<float2*>(&sBsq[s][ncol]);
                int idx = n0 + ncol;
                float k00 = fmaf(-2.0f, acc[g][0], b2.x);
                float k01 = fmaf(-2.0f, acc[g][1], b2.y);
                float k10 = fmaf(-2.0f, acc[g][2], b2.x);
                float k11 = fmaf(-2.0f, acc[g][3], b2.y);
                if (k00 < kmax0) topk_insert(td0, ti0, kmax0, k00, idx);
                if (k01 < kmax0) topk_insert(td0, ti0, kmax0, k01, idx + 1);
                if (k10 < kmax1) topk_insert(td1, ti1, kmax1, k10, idx);
                if (k11 < kmax1) topk_insert(td1, ti1, kmax1, k11, idx + 1);
            }
        }

        // store prefetched tile into the other buffer
        if (pf) {
            const int s1 = s ^ 1;
            { int c = tid;       int row = c >> 4, ch = c & 15;
                *reinterpret_cast<float4*>(pSB + s1 * BUFB + row * ROWB + ch * 16) = r0; }
            { int c = tid + 256; int row = c >> 4, ch = c & 15;
                *reinterpret_cast<float4*>(pSB + s1 * BUFB + row * ROWB + ch * 16) = r1; }
            { int c = tid + 512; int row = c >> 4, ch = c & 15;
                *reinterpret_cast<float4*>(pSB + s1 * BUFB + row * ROWB + ch * 16) = r2; }
            { int c = tid + 768; int row = c >> 4, ch = c & 15;
                *reinterpret_cast<float4*>(pSB + s1 * BUFB + row * ROWB + ch * 16) = r3; }
            if (tid < NT) sBsq[s ^ 1][tid] = rb;
        }
        __syncthreads();
    }

    // ---------------- end-of-kernel merge through smem (once) ----------------
    // layout: row-major [128 rows][stride 33 floats], 4 lanes x 8 slots each
    float* keysm = reinterpret_cast<float*>(pSB);              // 128*33*4 = 16896 B
    int*   idxsm = reinterpret_cast<int*>(pSB + 16896);        // 16896 B (tot 33792)
    {
        int l4 = lane & 3;
        int rlo = wid * 16 + (lane >> 2);
        int rhi = rlo + 8;
        #pragma unroll
        for (int j = 0; j < KPL; ++j) {
            keysm[rlo * 33 + l4 * 8 + j] = td0[j];
            idxsm[rlo * 33 + l4 * 8 + j] = ti0[j];
            keysm[rhi * 33 + l4 * 8 + j] = td1[j];
            idxsm[rhi * 33 + l4 * 8 + j] = ti1[j];
        }
    }
    __syncthreads();

    if (tid < 128) {
        float fd[KCC]; int fi[KCC];
        #pragma unroll
        for (int j = 0; j < KCC; ++j) { fd[j] = CUDART_INF_F; fi[j] = -1; }
        float fkmax = CUDART_INF_F;
        #pragma unroll
        for (int e = 0; e < 32; ++e) {
            float v = keysm[tid * 33 + e];
            if (v < fkmax) topk_insert(fd, fi, fkmax, v, idxsm[tid * 33 + e]);
        }
        int q = qt * 128 + tid;
        if (q < Q) {
            #pragma unroll
            for (int j = 0; j < KCC; ++j) {
                g_ckey[(chunk * KCC + j) * MAXQ + q] = fd[j];
                g_cidx[(chunk * KCC + j) * MAXQ + q] = fi[j];
            }
        }
    }
}

// ---------------------------------------------------------------------------
// Merge NC*16 chunk candidates -> global top-32 per query
// ---------------------------------------------------------------------------
__global__ void merge_kernel(int Q) {
    int q = blockIdx.x * blockDim.x + threadIdx.x;
    if (q >= Q) return;
    float td[KG]; int ti[KG];
    #pragma unroll
    for (int j = 0; j < KG; ++j) { td[j] = CUDART_INF_F; ti[j] = -1; }
    float kmax = CUDART_INF_F;
    for (int j = 0; j < NC * KCC; ++j) {
        float v = g_ckey[j * MAXQ + q];
        if (v < kmax) topk_insert(td, ti, kmax, v, g_cidx[j * MAXQ + q]);
    }
    #pragma unroll
    for (int j = 0; j < KG; ++j) g_sel[q * KG + j] = ti[j];
}

// ---------------------------------------------------------------------------
// Exact fp32 rescore of 32 candidates/query + final sort + output.
// ---------------------------------------------------------------------------
__global__ void rescore_kernel(const float* __restrict__ base,
                               const float* __restrict__ query,
                               float* __restrict__ out, int N, int Q, int K) {
    __shared__ float sD[4][KG];
    __shared__ int   sI[4][KG];
    int w = threadIdx.x >> 5;
    int lane = threadIdx.x & 31;
    int q = blockIdx.x * 4 + w;
    if (q >= Q) return;

    int cand = g_sel[q * KG + lane];
    float d2;
    if (cand >= 0) {
        const float4* qrow = reinterpret_cast<const float4*>(query) + (size_t)q * 32;
        const float4* brow = reinterpret_cast<const float4*>(base) + (size_t)cand * 32;
        float dot = 0.f, qsq = 0.f;
        #pragma unroll
        for (int j = 0; j < 32; ++j) {
            float4 a = qrow[j], b = brow[j];
            dot += a.x * b.x + a.y * b.y + a.z * b.z + a.w * b.w;
            qsq += a.x * a.x + a.y * a.y + a.z * a.z + a.w * a.w;
        }
        d2 = qsq - 2.0f * dot + g_bsq[cand];
    } else {
        d2 = CUDART_INF_F; cand = 0x7fffffff;
    }
    sD[w][lane] = d2; sI[w][lane] = cand;
    __syncwarp();

    if (lane == 0) {
        float a[KG]; int b[KG];
        #pragma unroll
        for (int j = 0; j < KG; ++j) { a[j] = sD[w][j]; b[j] = sI[w][j]; }
        for (int r = 0; r < K; ++r) {
            int best = r;
            for (int j = r + 1; j < KG; ++j)
                if (a[j] < a[best] || (a[j] == a[best] && b[j] < b[best])) best = j;
            float tv = a[r]; a[r] = a[best]; a[best] = tv;
            int   ts = b[r]; b[r] = b[best]; b[best] = ts;
            out[(size_t)q * K + r]                 = (float)b[r];
            out[(size_t)Q * K + (size_t)q * K + r] = sqrtf(fmaxf(a[r], 0.0f));
        }
    }
}

// ---------------------------------------------------------------------------
extern "C" void kernel_launch(void* const* d_in, const int* in_sizes, int n_in,
                              void* d_out, int out_size) {
    const float* base  = (const float*)d_in[0];
    const float* query = (const float*)d_in[1];

    int N = in_sizes[0] / D128;
    int Q = in_sizes[1] / D128;
    int K = (Q > 0) ? out_size / (2 * Q) : 10;
    if (K <= 0 || K > KG) K = 10;

    __nv_bfloat16* bhi; cudaGetSymbolAddress((void**)&bhi, g_bhi);
    __nv_bfloat16* qhi; cudaGetSymbolAddress((void**)&qhi, g_qhi);
    float* bsq;  cudaGetSymbolAddress((void**)&bsq, g_bsq);
    float* qsqd; cudaGetSymbolAddress((void**)&qsqd, g_qsq_dummy);

    bsqcvt_kernel<<<(N + 7) / 8, 256>>>(base, bhi, bsq, N);
    bsqcvt_kernel<<<(Q + 7) / 8, 256>>>(query, qhi, qsqd, Q);

    dim3 grid(NC, (Q + 127) / 128);
    knn_coarse<<<grid, 256>>>(bhi, qhi, N, Q);

    merge_kernel<<<(Q + 255) / 256, 256>>>(Q);
    rescore_kernel<<<(Q + 3) / 4, 128>>>(base, query, (float*)d_out, N, Q, K);
}

// round 9
// speedup vs baseline: 2.0829x; 1.0565x over previous
#include <cuda_runtime.h>
#include <cuda_bf16.h>
#include <math_constants.h>
#include <cstdint>

// ============================================================================
// Exact k-NN: int8 dp4a coarse scan + exact fp32 rescore.
//   1) quant:   s8 quantization (scale 25, clip +-127) + exact fp32 |row|^2
//   2) coarse:  thread-per-query dp4a scan (4 MACs/instr), per-thread top-16
//               per chunk on key = |b|^2 - (2/625)*dot_int
//   3) merge:   37 chunk lists -> global top-32 per query
//   4) rescore: exact fp32 d2 of 32 candidates, sort, emit top-k
// R9 = R8 resubmit (container infra failure, kernel never ran).
// ============================================================================

#define D128  128
#define NC    37        // base chunks
#define TB    64        // base rows per smem tile
#define KCC   16        // candidates per (query, chunk)
#define KG    32        // global coarse candidates per query
#define MAXN  262144
#define MAXQ  1024
#define QSCALE 25.0f
#define KEYSC (-2.0f / (QSCALE * QSCALE))   // -0.0032

__device__ __align__(256) uint32_t g_b8[MAXN * 32];   // 32 MB packed s8
__device__ __align__(256) uint32_t g_q8[MAXQ * 32];
__device__ float g_bsq[MAXN];
__device__ float g_qsq_dummy[MAXQ];
__device__ float g_ckey[NC * KCC * MAXQ];
__device__ int   g_cidx[NC * KCC * MAXQ];
__device__ int   g_sel [MAXQ * KG];

template<int K> __device__ __forceinline__
void topk_insert(float (&td)[K], int (&ti)[K], float& kmax, float v, int idx) {
    bool done = false;
    #pragma unroll
    for (int s = 0; s < K; ++s)
        if (!done && td[s] == kmax) { td[s] = v; ti[s] = idx; done = true; }
    float m = td[0];
    #pragma unroll
    for (int s = 1; s < K; ++s) m = fmaxf(m, td[s]);
    kmax = m;
}

// ---------------------------------------------------------------------------
// Quantize fp32 -> packed s8 (scale 25) + exact fp32 |row|^2. Warp per row.
// ---------------------------------------------------------------------------
__global__ void quant_kernel(const float* __restrict__ src,
                             uint32_t* __restrict__ dst8,
                             float* __restrict__ sq, int N) {
    int row = blockIdx.x * 8 + (threadIdx.x >> 5);
    if (row >= N) return;
    int lane = threadIdx.x & 31;
    float4 v = reinterpret_cast<const float4*>(src)[(size_t)row * 32 + lane];
    int i0 = __float2int_rn(fminf(fmaxf(v.x * QSCALE, -127.f), 127.f));
    int i1 = __float2int_rn(fminf(fmaxf(v.y * QSCALE, -127.f), 127.f));
    int i2 = __float2int_rn(fminf(fmaxf(v.z * QSCALE, -127.f), 127.f));
    int i3 = __float2int_rn(fminf(fmaxf(v.w * QSCALE, -127.f), 127.f));
    dst8[(size_t)row * 32 + lane] =
        (uint32_t)(i0 & 0xFF) | ((uint32_t)(i1 & 0xFF) << 8) |
        ((uint32_t)(i2 & 0xFF) << 16) | ((uint32_t)(i3 & 0xFF) << 24);
    float s = v.x * v.x + v.y * v.y + v.z * v.z + v.w * v.w;
    #pragma unroll
    for (int off = 16; off > 0; off >>= 1) s += __shfl_xor_sync(0xFFFFFFFFu, s, off);
    if (lane == 0) sq[row] = s;
}

// ---------------------------------------------------------------------------
// Coarse scan: grid (NC, Q/256), block 256, 1 thread = 1 query.
// Query row (128 s8 = 32 words) in registers; 64-row base tiles in smem
// (broadcast LDS), double-buffered with register prefetch, 1 barrier/tile.
// ---------------------------------------------------------------------------
__global__ void __launch_bounds__(256)
knn_coarse_i8(const uint32_t* __restrict__ b8,
              const uint32_t* __restrict__ q8,
              int N, int Q) {
    __shared__ __align__(16) uint32_t sB[2][TB * 32];   // 2 x 8 KB
    __shared__ float sBsq[2][TB];

    const int tid   = threadIdx.x;
    const int chunk = blockIdx.x;
    const int qt    = blockIdx.y;

    const int chunk_len = (N + NC - 1) / NC;
    const int cs = chunk * chunk_len;
    const int ce = min(cs + chunk_len, N);
    const int ntiles = (ce - cs + TB - 1) / TB;

    const uint4* b16 = reinterpret_cast<const uint4*>(b8);   // 8 uint4 per row

    // query row -> registers
    int qr[32];
    {
        int q = min(qt * 256 + tid, Q - 1);
        const uint32_t* qrow = q8 + (size_t)q * 32;
        #pragma unroll
        for (int i = 0; i < 32; ++i) qr[i] = (int)qrow[i];
    }

    float td[KCC]; int ti[KCC];
    #pragma unroll
    for (int j = 0; j < KCC; ++j) { td[j] = CUDART_INF_F; ti[j] = -1; }
    float kmax = CUDART_INF_F;

    // prologue: tile 0 -> buffer 0  (each thread: 2 uint4 of the 512)
    {
        { int c = tid;        int row = c >> 3, ch = c & 7;
          int gr = min(cs + row, N - 1);
          reinterpret_cast<uint4*>(&sB[0][0])[c] = b16[(size_t)gr * 8 + ch]; }
        { int c = tid + 256;  int row = c >> 3, ch = c & 7;
          int gr = min(cs + row, N - 1);
          reinterpret_cast<uint4*>(&sB[0][0])[c] = b16[(size_t)gr * 8 + ch]; }
        if (tid < TB) {
            int gr = cs + tid;
            sBsq[0][tid] = (gr < ce) ? g_bsq[gr] : CUDART_INF_F;
        }
        __syncthreads();
    }

    for (int t = 0; t < ntiles; ++t) {
        const int s = t & 1;
        const int n0 = cs + t * TB;
        const bool pf = (t + 1 < ntiles);

        // prefetch t+1 into registers (lands during dp4a phase)
        uint4 r0, r1; float rb = CUDART_INF_F;
        if (pf) {
            const int n0n = n0 + TB;
            { int c = tid;       int row = c >> 3, ch = c & 7;
              r0 = b16[(size_t)min(n0n + row, N - 1) * 8 + ch]; }
            { int c = tid + 256; int row = c >> 3, ch = c & 7;
              r1 = b16[(size_t)min(n0n + row, N - 1) * 8 + ch]; }
            if (tid < TB) {
                int gr = n0n + tid;
                rb = (gr < ce) ? g_bsq[gr] : CUDART_INF_F;
            }
        }

        // scan 64 rows: 8 LDS.128 + 32 dp4a (4 chains) + key per row
        const int vn = min(TB, ce - n0);
        #pragma unroll 2
        for (int r = 0; r < TB; ++r) {
            if (r >= vn) break;
            const uint4* b4 = reinterpret_cast<const uint4*>(&sB[s][r * 32]);
            uint4 bb0 = b4[0], bb1 = b4[1], bb2 = b4[2], bb3 = b4[3];
            uint4 bb4 = b4[4], bb5 = b4[5], bb6 = b4[6], bb7 = b4[7];
            int a0 = 0, a1 = 0, a2 = 0, a3 = 0;
            a0 = __dp4a((int)bb0.x, qr[0],  a0); a1 = __dp4a((int)bb0.y, qr[1],  a1);
            a2 = __dp4a((int)bb0.z, qr[2],  a2); a3 = __dp4a((int)bb0.w, qr[3],  a3);
            a0 = __dp4a((int)bb1.x, qr[4],  a0); a1 = __dp4a((int)bb1.y, qr[5],  a1);
            a2 = __dp4a((int)bb1.z, qr[6],  a2); a3 = __dp4a((int)bb1.w, qr[7],  a3);
            a0 = __dp4a((int)bb2.x, qr[8],  a0); a1 = __dp4a((int)bb2.y, qr[9],  a1);
            a2 = __dp4a((int)bb2.z, qr[10], a2); a3 = __dp4a((int)bb2.w, qr[11], a3);
            a0 = __dp4a((int)bb3.x, qr[12], a0); a1 = __dp4a((int)bb3.y, qr[13], a1);
            a2 = __dp4a((int)bb3.z, qr[14], a2); a3 = __dp4a((int)bb3.w, qr[15], a3);
            a0 = __dp4a((int)bb4.x, qr[16], a0); a1 = __dp4a((int)bb4.y, qr[17], a1);
            a2 = __dp4a((int)bb4.z, qr[18], a2); a3 = __dp4a((int)bb4.w, qr[19], a3);
            a0 = __dp4a((int)bb5.x, qr[20], a0); a1 = __dp4a((int)bb5.y, qr[21], a1);
            a2 = __dp4a((int)bb5.z, qr[22], a2); a3 = __dp4a((int)bb5.w, qr[23], a3);
            a0 = __dp4a((int)bb6.x, qr[24], a0); a1 = __dp4a((int)bb6.y, qr[25], a1);
            a2 = __dp4a((int)bb6.z, qr[26], a2); a3 = __dp4a((int)bb6.w, qr[27], a3);
            a0 = __dp4a((int)bb7.x, qr[28], a0); a1 = __dp4a((int)bb7.y, qr[29], a1);
            a2 = __dp4a((int)bb7.z, qr[30], a2); a3 = __dp4a((int)bb7.w, qr[31], a3);
            int dot = (a0 + a1) + (a2 + a3);
            float key = fmaf(KEYSC, __int2float_rn(dot), sBsq[s][r]);
            if (key < kmax) topk_insert(td, ti, kmax, key, n0 + r);
        }

        // store prefetched tile into other buffer, single barrier
        if (pf) {
            const int s1 = s ^ 1;
            reinterpret_cast<uint4*>(&sB[s1][0])[tid]       = r0;
            reinterpret_cast<uint4*>(&sB[s1][0])[tid + 256] = r1;
            if (tid < TB) sBsq[s1][tid] = rb;
        }
        __syncthreads();
    }

    // write candidates (transposed layout for coalesced merge reads)
    int q = qt * 256 + tid;
    if (q < Q) {
        #pragma unroll
        for (int j = 0; j < KCC; ++j) {
            g_ckey[(chunk * KCC + j) * MAXQ + q] = td[j];
            g_cidx[(chunk * KCC + j) * MAXQ + q] = ti[j];
        }
    }
}

// ---------------------------------------------------------------------------
// Merge NC*16 chunk candidates -> global top-32 per query
// ---------------------------------------------------------------------------
__global__ void merge_kernel(int Q) {
    int q = blockIdx.x * blockDim.x + threadIdx.x;
    if (q >= Q) return;
    float td[KG]; int ti[KG];
    #pragma unroll
    for (int j = 0; j < KG; ++j) { td[j] = CUDART_INF_F; ti[j] = -1; }
    float kmax = CUDART_INF_F;
    for (int j = 0; j < NC * KCC; ++j) {
        float v = g_ckey[j * MAXQ + q];
        if (v < kmax) topk_insert(td, ti, kmax, v, g_cidx[j * MAXQ + q]);
    }
    #pragma unroll
    for (int j = 0; j < KG; ++j) g_sel[q * KG + j] = ti[j];
}

// ---------------------------------------------------------------------------
// Exact fp32 rescore of 32 candidates/query + final sort + output.
// 1 warp per query, lane = candidate.
// ---------------------------------------------------------------------------
__global__ void rescore_kernel(const float* __restrict__ base,
                               const float* __restrict__ query,
                               float* __restrict__ out, int N, int Q, int K) {
    __shared__ float sD[4][KG];
    __shared__ int   sI[4][KG];
    int w = threadIdx.x >> 5;
    int lane = threadIdx.x & 31;
    int q = blockIdx.x * 4 + w;
    if (q >= Q) return;

    int cand = g_sel[q * KG + lane];
    float d2;
    if (cand >= 0) {
        const float4* qrow = reinterpret_cast<const float4*>(query) + (size_t)q * 32;
        const float4* brow = reinterpret_cast<const float4*>(base) + (size_t)cand * 32;
        float dot = 0.f, qsq = 0.f;
        #pragma unroll
        for (int j = 0; j < 32; ++j) {
            float4 a = qrow[j], b = brow[j];
            dot += a.x * b.x + a.y * b.y + a.z * b.z + a.w * b.w;
            qsq += a.x * a.x + a.y * a.y + a.z * a.z + a.w * a.w;
        }
        d2 = qsq - 2.0f * dot + g_bsq[cand];
    } else {
        d2 = CUDART_INF_F; cand = 0x7fffffff;
    }
    sD[w][lane] = d2; sI[w][lane] = cand;
    __syncwarp();

    if (lane == 0) {
        float a[KG]; int b[KG];
        #pragma unroll
        for (int j = 0; j < KG; ++j) { a[j] = sD[w][j]; b[j] = sI[w][j]; }
        for (int r = 0; r < K; ++r) {
            int best = r;
            for (int j = r + 1; j < KG; ++j)
                if (a[j] < a[best] || (a[j] == a[best] && b[j] < b[best])) best = j;
            float tv = a[r]; a[r] = a[best]; a[best] = tv;
            int   ts = b[r]; b[r] = b[best]; b[best] = ts;
            out[(size_t)q * K + r]                 = (float)b[r];
            out[(size_t)Q * K + (size_t)q * K + r] = sqrtf(fmaxf(a[r], 0.0f));
        }
    }
}

// ---------------------------------------------------------------------------
extern "C" void kernel_launch(void* const* d_in, const int* in_sizes, int n_in,
                              void* d_out, int out_size) {
    const float* base  = (const float*)d_in[0];
    const float* query = (const float*)d_in[1];

    int N = in_sizes[0] / D128;
    int Q = in_sizes[1] / D128;
    int K = (Q > 0) ? out_size / (2 * Q) : 10;
    if (K <= 0 || K > KG) K = 10;

    uint32_t* b8; cudaGetSymbolAddress((void**)&b8, g_b8);
    uint32_t* q8; cudaGetSymbolAddress((void**)&q8, g_q8);
    float* bsq;   cudaGetSymbolAddress((void**)&bsq, g_bsq);
    float* qsqd;  cudaGetSymbolAddress((void**)&qsqd, g_qsq_dummy);

    quant_kernel<<<(N + 7) / 8, 256>>>(base, b8, bsq, N);
    quant_kernel<<<(Q + 7) / 8, 256>>>(query, q8, qsqd, Q);

    dim3 grid(NC, (Q + 255) / 256);
    knn_coarse_i8<<<grid, 256>>>(b8, q8, N, Q);

    merge_kernel<<<(Q + 255) / 256, 256>>>(Q);
    rescore_kernel<<<(Q + 3) / 4, 128>>>(base, query, (float*)d_out, N, Q, K);
}